// round 7
// baseline (speedup 1.0000x reference)
#include <cuda_runtime.h>
#include <cuda_fp16.h>
#include <cstdint>
#include <cstddef>

// ---------------------------------------------------------------------------
// Problem constants
// ---------------------------------------------------------------------------
constexpr int B_ = 8, N_ = 2048, D_ = 1024, H_ = 2048;
constexpr int MTOT = B_ * N_;      // 16384
constexpr int SEGLEN = 512;

// Scratch (device globals; allocations forbidden)
__device__ __half g_xh [(size_t)MTOT * D_];
__device__ __half g_w1h[(size_t)4 * D_ * H_];
__device__ __half g_w3h[(size_t)4 * D_ * H_];
__device__ __half g_w2h[(size_t)4 * H_ * D_];
__device__ __half g_h  [(size_t)MTOT * H_];

// ---------------------------------------------------------------------------
// Helpers
// ---------------------------------------------------------------------------
__device__ __forceinline__ uint32_t smem_u32(const void* p) {
    uint32_t a;
    asm("{ .reg .u64 t; cvta.to.shared.u64 t, %1; cvt.u32.u64 %0, t; }"
        : "=r"(a) : "l"(p));
    return a;
}

#define CP_ASYNC16(dst, src) \
    asm volatile("cp.async.cg.shared.global [%0], [%1], 16;" :: "r"(dst), "l"(src))
#define CP_COMMIT() asm volatile("cp.async.commit_group;")
#define CP_WAIT1()  asm volatile("cp.async.wait_group 1;")

#define LDSM_X4(r0, r1, r2, r3, addr) \
    asm volatile("ldmatrix.sync.aligned.m8n8.x4.shared.b16 {%0,%1,%2,%3}, [%4];" \
                 : "=r"(r0), "=r"(r1), "=r"(r2), "=r"(r3) : "r"(addr))
#define LDSM_X4_T(r0, r1, r2, r3, addr) \
    asm volatile("ldmatrix.sync.aligned.m8n8.x4.trans.shared.b16 {%0,%1,%2,%3}, [%4];" \
                 : "=r"(r0), "=r"(r1), "=r"(r2), "=r"(r3) : "r"(addr))

#define MMA_16816(d, a, b0, b1) \
    asm volatile( \
        "mma.sync.aligned.m16n8k16.row.col.f32.f16.f16.f32 " \
        "{%0,%1,%2,%3}, {%4,%5,%6,%7}, {%8,%9}, {%0,%1,%2,%3};" \
        : "+f"((d)[0]), "+f"((d)[1]), "+f"((d)[2]), "+f"((d)[3]) \
        : "r"((a)[0]), "r"((a)[1]), "r"((a)[2]), "r"((a)[3]), \
          "r"(b0), "r"(b1))

// ---------------------------------------------------------------------------
// One-shot fp32 -> fp16 prepass: 8 floats (2 independent float4) per thread
// ---------------------------------------------------------------------------
__global__ void f2h_all_kernel(const float* __restrict__ x,
                               const float* __restrict__ w1,
                               const float* __restrict__ w3,
                               const float* __restrict__ w2,
                               __half* __restrict__ xh,
                               __half* __restrict__ w1h,
                               __half* __restrict__ w3h,
                               __half* __restrict__ w2h)
{
    constexpr long nx = (long)MTOT * D_;
    constexpr long nw = (long)4 * D_ * H_;
    long i = ((long)blockIdx.x * 256 + threadIdx.x) * 8;
    const float* s;
    __half* d;
    if (i < nx)               { s = x;  d = xh;  }
    else if (i < nx + nw)     { s = w1; d = w1h; i -= nx; }
    else if (i < nx + 2 * nw) { s = w3; d = w3h; i -= nx + nw; }
    else                      { s = w2; d = w2h; i -= nx + 2 * nw; }
    float4 v0 = *(const float4*)(s + i);
    float4 v1 = *(const float4*)(s + i + 4);
    __half2 a0 = __floats2half2_rn(v0.x, v0.y);
    __half2 a1 = __floats2half2_rn(v0.z, v0.w);
    __half2 a2 = __floats2half2_rn(v1.x, v1.y);
    __half2 a3 = __floats2half2_rn(v1.z, v1.w);
    uint4 r;
    r.x = *(const uint32_t*)&a0;
    r.y = *(const uint32_t*)&a1;
    r.z = *(const uint32_t*)&a2;
    r.w = *(const uint32_t*)&a3;
    *(uint4*)(d + i) = r;
}

// ---------------------------------------------------------------------------
// Fused GEMM1: h = silu(x @ w1[seg]) * (x @ w3[seg])
// CTA tile: 256(M) x 64(N per weight); 8 warps = 4M x 2N, warp 64x32/weight.
// MMA:LDSM ratio 4:1. BK=64, 3-stage cp.async pipeline (48KB/stage, 144KB).
// ---------------------------------------------------------------------------
__global__ void __launch_bounds__(256, 1)
ffn_fused_kernel(const __half* __restrict__ X,
                 const __half* __restrict__ W1,
                 const __half* __restrict__ W3,
                 __half* __restrict__ Hout)
{
    constexpr int STAGE_B = 49152;           // A 32KB + B1 8KB + B3 8KB
    constexpr int NK = D_ / 64;              // 16

    extern __shared__ __align__(1024) char smem[];
    const uint32_t sbase = smem_u32(smem);

    const int tid = threadIdx.x, lane = tid & 31, wid = tid >> 5;
    const int wm = wid >> 1, wn = wid & 1;           // 4M x 2N
    const int m0 = blockIdx.y * 256, n0 = blockIdx.x * 64;
    const int seg = (m0 % N_) / SEGLEN;              // 256 | 512: single segment

    const __half* gW1 = W1 + (size_t)seg * D_ * H_;
    const __half* gW3 = W3 + (size_t)seg * D_ * H_;

    auto load_stage = [&](int kt, int slot) {
        const uint32_t st = sbase + slot * STAGE_B;
        #pragma unroll
        for (int j = 0; j < 12; ++j) {               // 3072 chunks of 16B
            const int id = tid + j * 256;
            const __half* src;
            uint32_t dst;
            if (id < 2048) {                         // A: x tile [256][64]
                const int r = id >> 3, c = id & 7;
                src = X + (size_t)(m0 + r) * D_ + kt * 64 + c * 8;
                dst = st + r * 128 + ((c ^ (r & 7)) << 4);
            } else {                                 // B: w1/w3 [64][64] each
                const int id2 = id - 2048;
                const int w = id2 >> 9, k = (id2 >> 3) & 63, c = id2 & 7;
                const __half* wb = w ? gW3 : gW1;
                src = wb + (size_t)(kt * 64 + k) * H_ + n0 + c * 8;
                dst = st + 32768 + w * 8192 + k * 128 + ((c ^ (k & 7)) << 4);
            }
            CP_ASYNC16(dst, src);
        }
        CP_COMMIT();
    };

    const int lrow = ((lane >> 3) & 1) * 8 + (lane & 7);
    const int hi = lane >> 4;
    const int sw = lrow & 7;

    float acc[2][4][4][4];                           // [weight][mf][nf][e]
    #pragma unroll
    for (int w = 0; w < 2; ++w)
        #pragma unroll
        for (int mf = 0; mf < 4; ++mf)
            #pragma unroll
            for (int nf = 0; nf < 4; ++nf)
                #pragma unroll
                for (int e = 0; e < 4; ++e) acc[w][mf][nf][e] = 0.0f;

    load_stage(0, 0);
    load_stage(1, 1);

    for (int kt = 0; kt < NK; ++kt) {
        CP_WAIT1();
        __syncthreads();
        if (kt + 2 < NK) load_stage(kt + 2, (kt + 2) % 3);
        else CP_COMMIT();

        const uint32_t stA = sbase + (kt % 3) * STAGE_B;
        const uint32_t stB = stA + 32768;

        #pragma unroll
        for (int kk = 0; kk < 4; ++kk) {
            uint32_t a[4][4];
            #pragma unroll
            for (int mf = 0; mf < 4; ++mf) {
                const int r = wm * 64 + mf * 16 + lrow;
                const uint32_t ad =
                    stA + r * 128 + (((kk * 2 + hi) ^ sw) << 4);
                LDSM_X4(a[mf][0], a[mf][1], a[mf][2], a[mf][3], ad);
            }
            uint32_t b[2][2][4];
            #pragma unroll
            for (int w = 0; w < 2; ++w)
                #pragma unroll
                for (int j = 0; j < 2; ++j) {
                    const int krow = kk * 16 + lrow;
                    const int nchunk = wn * 4 + j * 2 + hi;
                    const uint32_t bd = stB + w * 8192 + krow * 128 +
                                        ((nchunk ^ sw) << 4);
                    LDSM_X4_T(b[w][j][0], b[w][j][1], b[w][j][2], b[w][j][3], bd);
                }
            #pragma unroll
            for (int w = 0; w < 2; ++w)
                #pragma unroll
                for (int mf = 0; mf < 4; ++mf)
                    #pragma unroll
                    for (int nf = 0; nf < 4; ++nf)
                        MMA_16816(acc[w][mf][nf], a[mf],
                                  b[w][nf >> 1][(nf & 1) * 2],
                                  b[w][nf >> 1][(nf & 1) * 2 + 1]);
        }
    }

    // epilogue: silu(acc[0]) * acc[1] -> fp16
    #pragma unroll
    for (int mf = 0; mf < 4; ++mf)
        #pragma unroll
        for (int nf = 0; nf < 4; ++nf)
            #pragma unroll
            for (int ep = 0; ep < 2; ++ep) {
                const int r = m0 + wm * 64 + mf * 16 + (lane >> 2) + ep * 8;
                const int c = n0 + wn * 32 + nf * 8 + (lane & 3) * 2;
                const float g0 = acc[0][mf][nf][ep * 2 + 0];
                const float g1 = acc[0][mf][nf][ep * 2 + 1];
                const float u0 = acc[1][mf][nf][ep * 2 + 0];
                const float u1 = acc[1][mf][nf][ep * 2 + 1];
                const float h0 = g0 * (1.0f / (1.0f + __expf(-g0))) * u0;
                const float h1 = g1 * (1.0f / (1.0f + __expf(-g1))) * u1;
                *(__half2*)(Hout + (size_t)r * H_ + c) = __floats2half2_rn(h0, h1);
            }
}

// ---------------------------------------------------------------------------
// GEMM2 (R3-proven): out = h @ w2[seg]  (fp32 out)
// Tile: 128(M) x 128(N), BK=64, 3-stage pipeline.
// 8 warps = 2(M) x 4(N); warp subtile 64x32. MMA:LDSM ratio 4:1.
// ---------------------------------------------------------------------------
__global__ void __launch_bounds__(256, 2)
gemm2_kernel(const __half* __restrict__ Hin,
             const __half* __restrict__ W2,
             float* __restrict__ Out)
{
    constexpr int STAGE_B = 32768;           // A 16KB + B 16KB
    constexpr int NK = H_ / 64;              // 32

    extern __shared__ __align__(1024) char smem[];
    const uint32_t sbase = smem_u32(smem);

    const int tid = threadIdx.x, lane = tid & 31, wid = tid >> 5;
    const int wm = wid >> 2, wn = wid & 3;
    const int m0 = blockIdx.y * 128, n0 = blockIdx.x * 128;
    const int seg = (m0 % N_) / SEGLEN;

    const __half* gW2 = W2 + (size_t)seg * H_ * D_;

    auto load_stage = [&](int kt, int slot) {
        const uint32_t st = sbase + slot * STAGE_B;
        #pragma unroll
        for (int j = 0; j < 8; ++j) {
            const int id = tid + j * 256;
            const __half* src;
            uint32_t dst;
            if (id < 1024) {                       // A: h tile [128][64]
                const int r = id >> 3, c = id & 7;
                src = Hin + (size_t)(m0 + r) * H_ + kt * 64 + c * 8;
                dst = st + r * 128 + ((c ^ (r & 7)) << 4);
            } else {                               // B: w2 tile [64][128]
                const int id2 = id - 1024;
                const int k = id2 >> 4, c = id2 & 15;
                src = gW2 + (size_t)(kt * 64 + k) * D_ + n0 + c * 8;
                dst = st + 16384 + k * 256 + ((c ^ (k & 7)) << 4);
            }
            CP_ASYNC16(dst, src);
        }
        CP_COMMIT();
    };

    const int lrow = ((lane >> 3) & 1) * 8 + (lane & 7);
    const int hi = lane >> 4;
    const int sw = lrow & 7;

    float acc[4][4][4];
    #pragma unroll
    for (int mf = 0; mf < 4; ++mf)
        #pragma unroll
        for (int nf = 0; nf < 4; ++nf)
            #pragma unroll
            for (int e = 0; e < 4; ++e) acc[mf][nf][e] = 0.0f;

    load_stage(0, 0);
    load_stage(1, 1);

    for (int kt = 0; kt < NK; ++kt) {
        CP_WAIT1();
        __syncthreads();
        if (kt + 2 < NK) load_stage(kt + 2, (kt + 2) % 3);
        else CP_COMMIT();

        const uint32_t stA = sbase + (kt % 3) * STAGE_B;
        const uint32_t stB = stA + 16384;

        #pragma unroll
        for (int kk = 0; kk < 4; ++kk) {
            uint32_t a[4][4];
            #pragma unroll
            for (int mf = 0; mf < 4; ++mf) {
                const int r = wm * 64 + mf * 16 + lrow;
                const uint32_t ad =
                    stA + r * 128 + (((kk * 2 + hi) ^ sw) << 4);
                LDSM_X4(a[mf][0], a[mf][1], a[mf][2], a[mf][3], ad);
            }
            uint32_t b[2][4];
            #pragma unroll
            for (int j = 0; j < 2; ++j) {
                const int krow = kk * 16 + lrow;
                const int nchunk = wn * 4 + j * 2 + hi;
                const uint32_t bd = stB + krow * 256 + ((nchunk ^ sw) << 4);
                LDSM_X4_T(b[j][0], b[j][1], b[j][2], b[j][3], bd);
            }
            #pragma unroll
            for (int mf = 0; mf < 4; ++mf)
                #pragma unroll
                for (int nf = 0; nf < 4; ++nf)
                    MMA_16816(acc[mf][nf], a[mf],
                              b[nf >> 1][(nf & 1) * 2],
                              b[nf >> 1][(nf & 1) * 2 + 1]);
        }
    }

    #pragma unroll
    for (int mf = 0; mf < 4; ++mf)
        #pragma unroll
        for (int nf = 0; nf < 4; ++nf)
            #pragma unroll
            for (int ep = 0; ep < 2; ++ep) {
                const int r = m0 + wm * 64 + mf * 16 + (lane >> 2) + ep * 8;
                const int c = n0 + wn * 32 + nf * 8 + (lane & 3) * 2;
                float2 v = make_float2(acc[mf][nf][ep * 2 + 0],
                                       acc[mf][nf][ep * 2 + 1]);
                *(float2*)(Out + (size_t)r * D_ + c) = v;
            }
}

// ---------------------------------------------------------------------------
extern "C" void kernel_launch(void* const* d_in, const int* in_sizes, int n_in,
                              void* d_out, int out_size)
{
    const float* x  = (const float*)d_in[0];
    const float* w1 = (const float*)d_in[1];
    const float* w3 = (const float*)d_in[2];
    const float* w2 = (const float*)d_in[3];
    float* out = (float*)d_out;

    __half *xh, *w1h, *w3h, *w2h, *h;
    cudaGetSymbolAddress((void**)&xh,  g_xh);
    cudaGetSymbolAddress((void**)&w1h, g_w1h);
    cudaGetSymbolAddress((void**)&w3h, g_w3h);
    cudaGetSymbolAddress((void**)&w2h, g_w2h);
    cudaGetSymbolAddress((void**)&h,   g_h);

    constexpr int SMEM1 = 3 * 49152;   // 144 KB
    constexpr int SMEM2 = 3 * 32768;   // 96 KB
    cudaFuncSetAttribute(ffn_fused_kernel,
                         cudaFuncAttributeMaxDynamicSharedMemorySize, SMEM1);
    cudaFuncSetAttribute(gemm2_kernel,
                         cudaFuncAttributeMaxDynamicSharedMemorySize, SMEM2);

    constexpr long TOT8 = ((long)MTOT * D_ + 3L * 4 * D_ * H_) / 8;
    f2h_all_kernel<<<(unsigned)(TOT8 / 256), 256>>>(x, w1, w3, w2,
                                                    xh, w1h, w3h, w2h);

    // h = silu(x @ w1[seg]) * (x @ w3[seg])
    ffn_fused_kernel<<<dim3(H_ / 64, MTOT / 256), 256, SMEM1>>>(xh, w1h, w3h, h);
    // out = h @ w2[seg]
    gemm2_kernel<<<dim3(D_ / 128, MTOT / 128), 256, SMEM2>>>(h, w2h, out);
}

// round 8
// speedup vs baseline: 1.0554x; 1.0554x over previous
#include <cuda_runtime.h>
#include <cuda_fp16.h>
#include <cstdint>
#include <cstddef>

// ---------------------------------------------------------------------------
// Problem constants
// ---------------------------------------------------------------------------
constexpr int B_ = 8, N_ = 2048, D_ = 1024, H_ = 2048;
constexpr int MTOT = B_ * N_;      // 16384
constexpr int SEGLEN = 512;

// Scratch (device globals; allocations forbidden)
__device__ __half g_xh [(size_t)MTOT * D_];
__device__ __half g_w1h[(size_t)4 * D_ * H_];
__device__ __half g_w3h[(size_t)4 * D_ * H_];
__device__ __half g_w2h[(size_t)4 * H_ * D_];
__device__ __half g_s  [(size_t)MTOT * H_];      // silu(x@w1)
__device__ __half g_h  [(size_t)MTOT * H_];      // s * (x@w3)

// ---------------------------------------------------------------------------
// Helpers
// ---------------------------------------------------------------------------
__device__ __forceinline__ uint32_t smem_u32(const void* p) {
    uint32_t a;
    asm("{ .reg .u64 t; cvta.to.shared.u64 t, %1; cvt.u32.u64 %0, t; }"
        : "=r"(a) : "l"(p));
    return a;
}

#define CP_ASYNC16(dst, src) \
    asm volatile("cp.async.cg.shared.global [%0], [%1], 16;" :: "r"(dst), "l"(src))
#define CP_COMMIT() asm volatile("cp.async.commit_group;")
#define CP_WAIT1()  asm volatile("cp.async.wait_group 1;")

#define LDSM_X4(r0, r1, r2, r3, addr) \
    asm volatile("ldmatrix.sync.aligned.m8n8.x4.shared.b16 {%0,%1,%2,%3}, [%4];" \
                 : "=r"(r0), "=r"(r1), "=r"(r2), "=r"(r3) : "r"(addr))
#define LDSM_X4_T(r0, r1, r2, r3, addr) \
    asm volatile("ldmatrix.sync.aligned.m8n8.x4.trans.shared.b16 {%0,%1,%2,%3}, [%4];" \
                 : "=r"(r0), "=r"(r1), "=r"(r2), "=r"(r3) : "r"(addr))

#define MMA_16816(d, a, b0, b1) \
    asm volatile( \
        "mma.sync.aligned.m16n8k16.row.col.f32.f16.f16.f32 " \
        "{%0,%1,%2,%3}, {%4,%5,%6,%7}, {%8,%9}, {%0,%1,%2,%3};" \
        : "+f"((d)[0]), "+f"((d)[1]), "+f"((d)[2]), "+f"((d)[3]) \
        : "r"((a)[0]), "r"((a)[1]), "r"((a)[2]), "r"((a)[3]), \
          "r"(b0), "r"(b1))

// ---------------------------------------------------------------------------
// One-shot fp32 -> fp16 prepass: 8 floats per thread (R6-proven, 81% DRAM)
// ---------------------------------------------------------------------------
__global__ void f2h_all_kernel(const float* __restrict__ x,
                               const float* __restrict__ w1,
                               const float* __restrict__ w3,
                               const float* __restrict__ w2,
                               __half* __restrict__ xh,
                               __half* __restrict__ w1h,
                               __half* __restrict__ w3h,
                               __half* __restrict__ w2h)
{
    constexpr long nx = (long)MTOT * D_;
    constexpr long nw = (long)4 * D_ * H_;
    long i = ((long)blockIdx.x * 256 + threadIdx.x) * 8;
    const float* s;
    __half* d;
    if (i < nx)               { s = x;  d = xh;  }
    else if (i < nx + nw)     { s = w1; d = w1h; i -= nx; }
    else if (i < nx + 2 * nw) { s = w3; d = w3h; i -= nx + nw; }
    else                      { s = w2; d = w2h; i -= nx + 2 * nw; }
    float4 v0 = *(const float4*)(s + i);
    float4 v1 = *(const float4*)(s + i + 4);
    __half2 a0 = __floats2half2_rn(v0.x, v0.y);
    __half2 a1 = __floats2half2_rn(v0.z, v0.w);
    __half2 a2 = __floats2half2_rn(v1.x, v1.y);
    __half2 a3 = __floats2half2_rn(v1.z, v1.w);
    uint4 r;
    r.x = *(const uint32_t*)&a0;
    r.y = *(const uint32_t*)&a1;
    r.z = *(const uint32_t*)&a2;
    r.w = *(const uint32_t*)&a3;
    *(uint4*)(d + i) = r;
}

// ---------------------------------------------------------------------------
// Generic GEMM in the R3-proven geometry:
//   C[M, NDIM] = A[M, KDIM] @ W[seg][KDIM, NDIM]
// Tile 128(M) x 128(N), BK=64, 3-stage cp.async pipeline.
// 8 warps = 2(M) x 4(N); warp subtile 64x32.
// EPI = 0: C = silu(acc)         -> fp16
// EPI = 1: C = Prev ⊙ acc        -> fp16   (Prev fp16, same shape as C)
// EPI = 2: C = acc               -> fp32
// ---------------------------------------------------------------------------
template <int EPI, int KDIM, int NDIM>
__global__ void __launch_bounds__(256, 2)
gemm128_kernel(const __half* __restrict__ A,
               const __half* __restrict__ W,      // [4][KDIM][NDIM]
               const __half* __restrict__ Prev,   // EPI==1 only
               void* __restrict__ Cout)
{
    constexpr int STAGE_B = 32768;           // A 16KB + B 16KB
    constexpr int NK = KDIM / 64;

    extern __shared__ __align__(1024) char smem[];
    const uint32_t sbase = smem_u32(smem);

    const int tid = threadIdx.x, lane = tid & 31, wid = tid >> 5;
    const int wm = wid >> 2, wn = wid & 3;
    const int m0 = blockIdx.y * 128, n0 = blockIdx.x * 128;
    const int seg = (m0 % N_) / SEGLEN;

    const __half* gW = W + (size_t)seg * KDIM * NDIM;

    auto load_stage = [&](int kt, int slot) {
        const uint32_t st = sbase + slot * STAGE_B;
        #pragma unroll
        for (int j = 0; j < 8; ++j) {
            const int id = tid + j * 256;
            const __half* src;
            uint32_t dst;
            if (id < 1024) {                       // A tile [128][64]
                const int r = id >> 3, c = id & 7;
                src = A + (size_t)(m0 + r) * KDIM + kt * 64 + c * 8;
                dst = st + r * 128 + ((c ^ (r & 7)) << 4);
            } else {                               // B tile [64][128]
                const int id2 = id - 1024;
                const int k = id2 >> 4, c = id2 & 15;
                src = gW + (size_t)(kt * 64 + k) * NDIM + n0 + c * 8;
                dst = st + 16384 + k * 256 + ((c ^ (k & 7)) << 4);
            }
            CP_ASYNC16(dst, src);
        }
        CP_COMMIT();
    };

    const int lrow = ((lane >> 3) & 1) * 8 + (lane & 7);
    const int hi = lane >> 4;
    const int sw = lrow & 7;

    float acc[4][4][4];
    #pragma unroll
    for (int mf = 0; mf < 4; ++mf)
        #pragma unroll
        for (int nf = 0; nf < 4; ++nf)
            #pragma unroll
            for (int e = 0; e < 4; ++e) acc[mf][nf][e] = 0.0f;

    load_stage(0, 0);
    load_stage(1, 1);

    for (int kt = 0; kt < NK; ++kt) {
        CP_WAIT1();
        __syncthreads();
        if (kt + 2 < NK) load_stage(kt + 2, (kt + 2) % 3);
        else CP_COMMIT();

        const uint32_t stA = sbase + (kt % 3) * STAGE_B;
        const uint32_t stB = stA + 16384;

        #pragma unroll
        for (int kk = 0; kk < 4; ++kk) {
            uint32_t a[4][4];
            #pragma unroll
            for (int mf = 0; mf < 4; ++mf) {
                const int r = wm * 64 + mf * 16 + lrow;
                const uint32_t ad =
                    stA + r * 128 + (((kk * 2 + hi) ^ sw) << 4);
                LDSM_X4(a[mf][0], a[mf][1], a[mf][2], a[mf][3], ad);
            }
            uint32_t b[2][4];
            #pragma unroll
            for (int j = 0; j < 2; ++j) {
                const int krow = kk * 16 + lrow;
                const int nchunk = wn * 4 + j * 2 + hi;
                const uint32_t bd = stB + krow * 256 + ((nchunk ^ sw) << 4);
                LDSM_X4_T(b[j][0], b[j][1], b[j][2], b[j][3], bd);
            }
            #pragma unroll
            for (int mf = 0; mf < 4; ++mf)
                #pragma unroll
                for (int nf = 0; nf < 4; ++nf)
                    MMA_16816(acc[mf][nf], a[mf],
                              b[nf >> 1][(nf & 1) * 2],
                              b[nf >> 1][(nf & 1) * 2 + 1]);
        }
    }

    // Epilogue
    #pragma unroll
    for (int mf = 0; mf < 4; ++mf)
        #pragma unroll
        for (int nf = 0; nf < 4; ++nf)
            #pragma unroll
            for (int ep = 0; ep < 2; ++ep) {
                const int r = m0 + wm * 64 + mf * 16 + (lane >> 2) + ep * 8;
                const int c = n0 + wn * 32 + nf * 8 + (lane & 3) * 2;
                const float v0 = acc[mf][nf][ep * 2 + 0];
                const float v1 = acc[mf][nf][ep * 2 + 1];
                if (EPI == 0) {
                    const float s0 = v0 * (1.0f / (1.0f + __expf(-v0)));
                    const float s1 = v1 * (1.0f / (1.0f + __expf(-v1)));
                    *(__half2*)((__half*)Cout + (size_t)r * NDIM + c) =
                        __floats2half2_rn(s0, s1);
                } else if (EPI == 1) {
                    const __half2 p =
                        *(const __half2*)(Prev + (size_t)r * NDIM + c);
                    const float2 pf = __half22float2(p);
                    *(__half2*)((__half*)Cout + (size_t)r * NDIM + c) =
                        __floats2half2_rn(pf.x * v0, pf.y * v1);
                } else {
                    *(float2*)((float*)Cout + (size_t)r * NDIM + c) =
                        make_float2(v0, v1);
                }
            }
}

// ---------------------------------------------------------------------------
extern "C" void kernel_launch(void* const* d_in, const int* in_sizes, int n_in,
                              void* d_out, int out_size)
{
    const float* x  = (const float*)d_in[0];
    const float* w1 = (const float*)d_in[1];
    const float* w3 = (const float*)d_in[2];
    const float* w2 = (const float*)d_in[3];
    float* out = (float*)d_out;

    __half *xh, *w1h, *w3h, *w2h, *s, *h;
    cudaGetSymbolAddress((void**)&xh,  g_xh);
    cudaGetSymbolAddress((void**)&w1h, g_w1h);
    cudaGetSymbolAddress((void**)&w3h, g_w3h);
    cudaGetSymbolAddress((void**)&w2h, g_w2h);
    cudaGetSymbolAddress((void**)&s,   g_s);
    cudaGetSymbolAddress((void**)&h,   g_h);

    constexpr int SMEM = 3 * 32768;   // 96 KB
    cudaFuncSetAttribute(gemm128_kernel<0, D_, H_>,
                         cudaFuncAttributeMaxDynamicSharedMemorySize, SMEM);
    cudaFuncSetAttribute(gemm128_kernel<1, D_, H_>,
                         cudaFuncAttributeMaxDynamicSharedMemorySize, SMEM);
    cudaFuncSetAttribute(gemm128_kernel<2, H_, D_>,
                         cudaFuncAttributeMaxDynamicSharedMemorySize, SMEM);

    constexpr long TOT8 = ((long)MTOT * D_ + 3L * 4 * D_ * H_) / 8;
    f2h_all_kernel<<<(unsigned)(TOT8 / 256), 256>>>(x, w1, w3, w2,
                                                    xh, w1h, w3h, w2h);

    dim3 gUp(H_ / 128, MTOT / 128);   // 16 x 128
    dim3 gDn(D_ / 128, MTOT / 128);   //  8 x 128

    // s = silu(x @ w1[seg])
    gemm128_kernel<0, D_, H_><<<gUp, 256, SMEM>>>(xh, w1h, nullptr, s);
    // h = s * (x @ w3[seg])
    gemm128_kernel<1, D_, H_><<<gUp, 256, SMEM>>>(xh, w3h, s, h);
    // out = h @ w2[seg]
    gemm128_kernel<2, H_, D_><<<gDn, 256, SMEM>>>(h, w2h, nullptr, out);
}

// round 9
// speedup vs baseline: 1.1570x; 1.0963x over previous
#include <cuda_runtime.h>
#include <cuda_fp16.h>
#include <cstdint>
#include <cstddef>

// ---------------------------------------------------------------------------
// Problem constants
// ---------------------------------------------------------------------------
constexpr int B_ = 8, N_ = 2048, D_ = 1024, H_ = 2048;
constexpr int MTOT = B_ * N_;      // 16384
constexpr int SEGLEN = 512;

// Scratch (device globals; allocations forbidden)
__device__ __half g_xh [(size_t)MTOT * D_];
__device__ __half g_w1h[(size_t)4 * D_ * H_];
__device__ __half g_w3h[(size_t)4 * D_ * H_];
__device__ __half g_w2h[(size_t)4 * H_ * D_];
__device__ __half g_h  [(size_t)MTOT * H_];

// ---------------------------------------------------------------------------
// Helpers
// ---------------------------------------------------------------------------
__device__ __forceinline__ uint32_t smem_u32(const void* p) {
    uint32_t a;
    asm("{ .reg .u64 t; cvta.to.shared.u64 t, %1; cvt.u32.u64 %0, t; }"
        : "=r"(a) : "l"(p));
    return a;
}

#define CP_ASYNC16(dst, src) \
    asm volatile("cp.async.cg.shared.global [%0], [%1], 16;" :: "r"(dst), "l"(src))
#define CP_COMMIT() asm volatile("cp.async.commit_group;")
#define CP_WAIT1()  asm volatile("cp.async.wait_group 1;")

#define LDSM_X4(r0, r1, r2, r3, addr) \
    asm volatile("ldmatrix.sync.aligned.m8n8.x4.shared.b16 {%0,%1,%2,%3}, [%4];" \
                 : "=r"(r0), "=r"(r1), "=r"(r2), "=r"(r3) : "r"(addr))
#define LDSM_X4_T(r0, r1, r2, r3, addr) \
    asm volatile("ldmatrix.sync.aligned.m8n8.x4.trans.shared.b16 {%0,%1,%2,%3}, [%4];" \
                 : "=r"(r0), "=r"(r1), "=r"(r2), "=r"(r3) : "r"(addr))

#define MMA_16816(d, a, b0, b1) \
    asm volatile( \
        "mma.sync.aligned.m16n8k16.row.col.f32.f16.f16.f32 " \
        "{%0,%1,%2,%3}, {%4,%5,%6,%7}, {%8,%9}, {%0,%1,%2,%3};" \
        : "+f"((d)[0]), "+f"((d)[1]), "+f"((d)[2]), "+f"((d)[3]) \
        : "r"((a)[0]), "r"((a)[1]), "r"((a)[2]), "r"((a)[3]), \
          "r"(b0), "r"(b1))

// ---------------------------------------------------------------------------
// One-shot fp32 -> fp16 prepass: 8 floats per thread (R6-proven, 81% DRAM)
// ---------------------------------------------------------------------------
__global__ void f2h_all_kernel(const float* __restrict__ x,
                               const float* __restrict__ w1,
                               const float* __restrict__ w3,
                               const float* __restrict__ w2,
                               __half* __restrict__ xh,
                               __half* __restrict__ w1h,
                               __half* __restrict__ w3h,
                               __half* __restrict__ w2h)
{
    constexpr long nx = (long)MTOT * D_;
    constexpr long nw = (long)4 * D_ * H_;
    long i = ((long)blockIdx.x * 256 + threadIdx.x) * 8;
    const float* s;
    __half* d;
    if (i < nx)               { s = x;  d = xh;  }
    else if (i < nx + nw)     { s = w1; d = w1h; i -= nx; }
    else if (i < nx + 2 * nw) { s = w3; d = w3h; i -= nx + nw; }
    else                      { s = w2; d = w2h; i -= nx + 2 * nw; }
    float4 v0 = *(const float4*)(s + i);
    float4 v1 = *(const float4*)(s + i + 4);
    __half2 a0 = __floats2half2_rn(v0.x, v0.y);
    __half2 a1 = __floats2half2_rn(v0.z, v0.w);
    __half2 a2 = __floats2half2_rn(v1.x, v1.y);
    __half2 a3 = __floats2half2_rn(v1.z, v1.w);
    uint4 r;
    r.x = *(const uint32_t*)&a0;
    r.y = *(const uint32_t*)&a1;
    r.z = *(const uint32_t*)&a2;
    r.w = *(const uint32_t*)&a3;
    *(uint4*)(d + i) = r;
}

// ---------------------------------------------------------------------------
// Fused GEMM1 (R3-proven, 512us config): h = silu(x @ w1[seg]) * (x @ w3[seg])
// Tile: 128(M) x 64(N per weight), BK=64, 3-stage cp.async pipeline.
// 8 warps = 4(M) x 2(N); warp subtile 32x32 per weight.
// ---------------------------------------------------------------------------
__global__ void __launch_bounds__(256, 2)
ffn_fused_kernel(const __half* __restrict__ X,
                 const __half* __restrict__ W1,
                 const __half* __restrict__ W3,
                 __half* __restrict__ Hout)
{
    constexpr int STAGE_B = 32768;           // A 16KB + B1 8KB + B3 8KB
    constexpr int NK = D_ / 64;              // 16

    extern __shared__ __align__(1024) char smem[];
    const uint32_t sbase = smem_u32(smem);

    const int tid = threadIdx.x, lane = tid & 31, wid = tid >> 5;
    const int wm = wid >> 1, wn = wid & 1;
    const int m0 = blockIdx.y * 128, n0 = blockIdx.x * 64;
    const int seg = (m0 % N_) / SEGLEN;

    const __half* gW1 = W1 + (size_t)seg * D_ * H_;
    const __half* gW3 = W3 + (size_t)seg * D_ * H_;

    auto load_stage = [&](int kt, int slot) {
        const uint32_t st = sbase + slot * STAGE_B;
        #pragma unroll
        for (int j = 0; j < 8; ++j) {
            const int id = tid + j * 256;
            const __half* src;
            uint32_t dst;
            if (id < 1024) {                       // A: x tile [128][64]
                const int r = id >> 3, c = id & 7;
                src = X + (size_t)(m0 + r) * D_ + kt * 64 + c * 8;
                dst = st + r * 128 + ((c ^ (r & 7)) << 4);
            } else {                               // B: weights [64][64] each
                const int id2 = id - 1024;
                const int w = id2 >> 9, k = (id2 >> 3) & 63, c = id2 & 7;
                const __half* wb = w ? gW3 : gW1;
                src = wb + (size_t)(kt * 64 + k) * H_ + n0 + c * 8;
                dst = st + 16384 + w * 8192 + k * 128 + ((c ^ (k & 7)) << 4);
            }
            CP_ASYNC16(dst, src);
        }
        CP_COMMIT();
    };

    const int lrow = ((lane >> 3) & 1) * 8 + (lane & 7);
    const int hi = lane >> 4;
    const int sw = lrow & 7;

    float acc[2][2][4][4];
    #pragma unroll
    for (int w = 0; w < 2; ++w)
        #pragma unroll
        for (int mf = 0; mf < 2; ++mf)
            #pragma unroll
            for (int nf = 0; nf < 4; ++nf)
                #pragma unroll
                for (int e = 0; e < 4; ++e) acc[w][mf][nf][e] = 0.0f;

    load_stage(0, 0);
    load_stage(1, 1);

    for (int kt = 0; kt < NK; ++kt) {
        CP_WAIT1();
        __syncthreads();
        if (kt + 2 < NK) load_stage(kt + 2, (kt + 2) % 3);
        else CP_COMMIT();

        const uint32_t stA = sbase + (kt % 3) * STAGE_B;
        const uint32_t stB = stA + 16384;

        #pragma unroll
        for (int kk = 0; kk < 4; ++kk) {
            uint32_t a[2][4];
            #pragma unroll
            for (int mf = 0; mf < 2; ++mf) {
                const int r = wm * 32 + mf * 16 + lrow;
                const uint32_t ad =
                    stA + r * 128 + (((kk * 2 + hi) ^ sw) << 4);
                LDSM_X4(a[mf][0], a[mf][1], a[mf][2], a[mf][3], ad);
            }
            uint32_t b[2][2][4];
            #pragma unroll
            for (int w = 0; w < 2; ++w)
                #pragma unroll
                for (int j = 0; j < 2; ++j) {
                    const int krow = kk * 16 + lrow;
                    const int nchunk = wn * 4 + j * 2 + hi;
                    const uint32_t bd = stB + w * 8192 + krow * 128 +
                                        ((nchunk ^ sw) << 4);
                    LDSM_X4_T(b[w][j][0], b[w][j][1], b[w][j][2], b[w][j][3], bd);
                }
            #pragma unroll
            for (int w = 0; w < 2; ++w)
                #pragma unroll
                for (int mf = 0; mf < 2; ++mf)
                    #pragma unroll
                    for (int nf = 0; nf < 4; ++nf)
                        MMA_16816(acc[w][mf][nf], a[mf],
                                  b[w][nf >> 1][(nf & 1) * 2],
                                  b[w][nf >> 1][(nf & 1) * 2 + 1]);
        }
    }

    // epilogue: silu(acc[0]) * acc[1] -> fp16
    #pragma unroll
    for (int mf = 0; mf < 2; ++mf)
        #pragma unroll
        for (int nf = 0; nf < 4; ++nf)
            #pragma unroll
            for (int ep = 0; ep < 2; ++ep) {
                const int r = m0 + wm * 32 + mf * 16 + (lane >> 2) + ep * 8;
                const int c = n0 + wn * 32 + nf * 8 + (lane & 3) * 2;
                const float g0 = acc[0][mf][nf][ep * 2 + 0];
                const float g1 = acc[0][mf][nf][ep * 2 + 1];
                const float u0 = acc[1][mf][nf][ep * 2 + 0];
                const float u1 = acc[1][mf][nf][ep * 2 + 1];
                const float h0 = g0 * (1.0f / (1.0f + __expf(-g0))) * u0;
                const float h1 = g1 * (1.0f / (1.0f + __expf(-g1))) * u1;
                *(__half2*)(Hout + (size_t)r * H_ + c) = __floats2half2_rn(h0, h1);
            }
}

// ---------------------------------------------------------------------------
// GEMM2 (R3-proven, 433 TF/s measured): out = h @ w2[seg]  (fp32 out)
// Tile: 128(M) x 128(N), BK=64, 3-stage pipeline.
// 8 warps = 2(M) x 4(N); warp subtile 64x32.
// ---------------------------------------------------------------------------
__global__ void __launch_bounds__(256, 2)
gemm2_kernel(const __half* __restrict__ Hin,
             const __half* __restrict__ W2,
             float* __restrict__ Out)
{
    constexpr int STAGE_B = 32768;           // A 16KB + B 16KB
    constexpr int NK = H_ / 64;              // 32

    extern __shared__ __align__(1024) char smem[];
    const uint32_t sbase = smem_u32(smem);

    const int tid = threadIdx.x, lane = tid & 31, wid = tid >> 5;
    const int wm = wid >> 2, wn = wid & 3;
    const int m0 = blockIdx.y * 128, n0 = blockIdx.x * 128;
    const int seg = (m0 % N_) / SEGLEN;

    const __half* gW2 = W2 + (size_t)seg * H_ * D_;

    auto load_stage = [&](int kt, int slot) {
        const uint32_t st = sbase + slot * STAGE_B;
        #pragma unroll
        for (int j = 0; j < 8; ++j) {
            const int id = tid + j * 256;
            const __half* src;
            uint32_t dst;
            if (id < 1024) {                       // A: h tile [128][64]
                const int r = id >> 3, c = id & 7;
                src = Hin + (size_t)(m0 + r) * H_ + kt * 64 + c * 8;
                dst = st + r * 128 + ((c ^ (r & 7)) << 4);
            } else {                               // B: w2 tile [64][128]
                const int id2 = id - 1024;
                const int k = id2 >> 4, c = id2 & 15;
                src = gW2 + (size_t)(kt * 64 + k) * D_ + n0 + c * 8;
                dst = st + 16384 + k * 256 + ((c ^ (k & 7)) << 4);
            }
            CP_ASYNC16(dst, src);
        }
        CP_COMMIT();
    };

    const int lrow = ((lane >> 3) & 1) * 8 + (lane & 7);
    const int hi = lane >> 4;
    const int sw = lrow & 7;

    float acc[4][4][4];
    #pragma unroll
    for (int mf = 0; mf < 4; ++mf)
        #pragma unroll
        for (int nf = 0; nf < 4; ++nf)
            #pragma unroll
            for (int e = 0; e < 4; ++e) acc[mf][nf][e] = 0.0f;

    load_stage(0, 0);
    load_stage(1, 1);

    for (int kt = 0; kt < NK; ++kt) {
        CP_WAIT1();
        __syncthreads();
        if (kt + 2 < NK) load_stage(kt + 2, (kt + 2) % 3);
        else CP_COMMIT();

        const uint32_t stA = sbase + (kt % 3) * STAGE_B;
        const uint32_t stB = stA + 16384;

        #pragma unroll
        for (int kk = 0; kk < 4; ++kk) {
            uint32_t a[4][4];
            #pragma unroll
            for (int mf = 0; mf < 4; ++mf) {
                const int r = wm * 64 + mf * 16 + lrow;
                const uint32_t ad =
                    stA + r * 128 + (((kk * 2 + hi) ^ sw) << 4);
                LDSM_X4(a[mf][0], a[mf][1], a[mf][2], a[mf][3], ad);
            }
            uint32_t b[2][4];
            #pragma unroll
            for (int j = 0; j < 2; ++j) {
                const int krow = kk * 16 + lrow;
                const int nchunk = wn * 4 + j * 2 + hi;
                const uint32_t bd = stB + krow * 256 + ((nchunk ^ sw) << 4);
                LDSM_X4_T(b[j][0], b[j][1], b[j][2], b[j][3], bd);
            }
            #pragma unroll
            for (int mf = 0; mf < 4; ++mf)
                #pragma unroll
                for (int nf = 0; nf < 4; ++nf)
                    MMA_16816(acc[mf][nf], a[mf],
                              b[nf >> 1][(nf & 1) * 2],
                              b[nf >> 1][(nf & 1) * 2 + 1]);
        }
    }

    #pragma unroll
    for (int mf = 0; mf < 4; ++mf)
        #pragma unroll
        for (int nf = 0; nf < 4; ++nf)
            #pragma unroll
            for (int ep = 0; ep < 2; ++ep) {
                const int r = m0 + wm * 64 + mf * 16 + (lane >> 2) + ep * 8;
                const int c = n0 + wn * 32 + nf * 8 + (lane & 3) * 2;
                float2 v = make_float2(acc[mf][nf][ep * 2 + 0],
                                       acc[mf][nf][ep * 2 + 1]);
                *(float2*)(Out + (size_t)r * D_ + c) = v;
            }
}

// ---------------------------------------------------------------------------
extern "C" void kernel_launch(void* const* d_in, const int* in_sizes, int n_in,
                              void* d_out, int out_size)
{
    const float* x  = (const float*)d_in[0];
    const float* w1 = (const float*)d_in[1];
    const float* w3 = (const float*)d_in[2];
    const float* w2 = (const float*)d_in[3];
    float* out = (float*)d_out;

    __half *xh, *w1h, *w3h, *w2h, *h;
    cudaGetSymbolAddress((void**)&xh,  g_xh);
    cudaGetSymbolAddress((void**)&w1h, g_w1h);
    cudaGetSymbolAddress((void**)&w3h, g_w3h);
    cudaGetSymbolAddress((void**)&w2h, g_w2h);
    cudaGetSymbolAddress((void**)&h,   g_h);

    constexpr int SMEM = 3 * 32768;   // 96 KB
    cudaFuncSetAttribute(ffn_fused_kernel,
                         cudaFuncAttributeMaxDynamicSharedMemorySize, SMEM);
    cudaFuncSetAttribute(gemm2_kernel,
                         cudaFuncAttributeMaxDynamicSharedMemorySize, SMEM);

    constexpr long TOT8 = ((long)MTOT * D_ + 3L * 4 * D_ * H_) / 8;
    f2h_all_kernel<<<(unsigned)(TOT8 / 256), 256>>>(x, w1, w3, w2,
                                                    xh, w1h, w3h, w2h);

    // h = silu(x @ w1[seg]) * (x @ w3[seg])
    ffn_fused_kernel<<<dim3(H_ / 64, MTOT / 128), 256, SMEM>>>(xh, w1h, w3h, h);
    // out = h @ w2[seg]
    gemm2_kernel<<<dim3(D_ / 128, MTOT / 128), 256, SMEM>>>(h, w2h, out);
}